// round 2
// baseline (speedup 1.0000x reference)
#include <cuda_runtime.h>

#define NTHREADS 256
#define HID 32
#define NB 4
#define DIN 3

__device__ __forceinline__ unsigned long long fma2(unsigned long long a,
                                                   unsigned long long b,
                                                   unsigned long long c) {
    unsigned long long d;
    asm("fma.rn.f32x2 %0, %1, %2, %3;" : "=l"(d) : "l"(a), "l"(b), "l"(c));
    return d;
}

__device__ __forceinline__ unsigned long long pack2(float lo, float hi) {
    unsigned long long r;
    asm("mov.b64 %0, {%1, %2};" : "=l"(r) : "f"(lo), "f"(hi));
    return r;
}

__device__ __forceinline__ void unpack2(unsigned long long v, float& lo, float& hi) {
    asm("mov.b64 {%0, %1}, %2;" : "=f"(lo), "=f"(hi) : "l"(v));
}

// tanh(x) = 1 - 2/(exp(2x)+1); saturates correctly: exp->inf => 1, exp->0 => -1.
__device__ __forceinline__ float fast_tanh(float v) {
    float e = __expf(2.0f * v);
    return 1.0f - __fdividef(2.0f, e + 1.0f);
}

// One 32->32 dense layer + tanh. w is [32][32] row-major (d-major), bias [32].
// hin/hout are register arrays (fully unrolled).
__device__ __forceinline__ void dense32_tanh(const float* __restrict__ w,
                                             const float* __restrict__ bias,
                                             const float* __restrict__ hin,
                                             float* __restrict__ hout) {
    unsigned long long acc[16];
    const unsigned long long* bp = (const unsigned long long*)bias;
#pragma unroll
    for (int j = 0; j < 16; j++) acc[j] = bp[j];
#pragma unroll
    for (int d = 0; d < HID; d++) {
        unsigned long long hh = pack2(hin[d], hin[d]);
        const ulonglong2* wr = (const ulonglong2*)(w + d * HID);
#pragma unroll
        for (int j2 = 0; j2 < 8; j2++) {
            ulonglong2 wv = wr[j2];
            acc[2 * j2]     = fma2(hh, wv.x, acc[2 * j2]);
            acc[2 * j2 + 1] = fma2(hh, wv.y, acc[2 * j2 + 1]);
        }
    }
#pragma unroll
    for (int j = 0; j < 16; j++) {
        float lo, hi;
        unpack2(acc[j], lo, hi);
        hout[2 * j]     = fast_tanh(lo);
        hout[2 * j + 1] = fast_tanh(hi);
    }
}

__global__ void __launch_bounds__(NTHREADS, 2) pfnn_kernel(
    const float* __restrict__ x,
    const float* __restrict__ gW0, const float* __restrict__ gb0,
    const float* __restrict__ gW1, const float* __restrict__ gb1,
    const float* __restrict__ gW2, const float* __restrict__ gb2,
    const float* __restrict__ gW3, const float* __restrict__ gb3,
    float* __restrict__ out, int n) {
    __shared__ __align__(16) float sW0[NB][DIN][HID];
    __shared__ __align__(16) float sb0[NB][HID];
    __shared__ __align__(16) float sW1[NB][HID][HID];
    __shared__ __align__(16) float sb1[NB][HID];
    __shared__ __align__(16) float sW2[NB][HID][HID];
    __shared__ __align__(16) float sb2[NB][HID];
    __shared__ __align__(16) float sW3[NB][HID];
    __shared__ __align__(16) float sb3[NB];

    const int tid = threadIdx.x;
    for (int i = tid; i < NB * DIN * HID; i += NTHREADS) (&sW0[0][0][0])[i] = gW0[i];
    for (int i = tid; i < NB * HID; i += NTHREADS) (&sb0[0][0])[i] = gb0[i];
    for (int i = tid; i < NB * HID * HID; i += NTHREADS) (&sW1[0][0][0])[i] = gW1[i];
    for (int i = tid; i < NB * HID; i += NTHREADS) (&sb1[0][0])[i] = gb1[i];
    for (int i = tid; i < NB * HID * HID; i += NTHREADS) (&sW2[0][0][0])[i] = gW2[i];
    for (int i = tid; i < NB * HID; i += NTHREADS) (&sb2[0][0])[i] = gb2[i];
    for (int i = tid; i < NB * HID; i += NTHREADS) (&sW3[0][0])[i] = gW3[i];
    for (int i = tid; i < NB; i += NTHREADS) sb3[i] = gb3[i];
    __syncthreads();

    const int idx = blockIdx.x * NTHREADS + tid;
    if (idx >= n) return;

    const float x0 = x[idx * 3 + 0];
    const float x1 = x[idx * 3 + 1];
    const float x2 = x[idx * 3 + 2];
    const unsigned long long xx0 = pack2(x0, x0);
    const unsigned long long xx1 = pack2(x1, x1);
    const unsigned long long xx2 = pack2(x2, x2);

#pragma unroll 1
    for (int b = 0; b < NB; ++b) {
        // ---- layer 0: 3 -> 32, tanh ----
        unsigned long long acc[16];
        const unsigned long long* bp = (const unsigned long long*)sb0[b];
#pragma unroll
        for (int j = 0; j < 16; j++) acc[j] = bp[j];
        {
            const ulonglong2* w0r = (const ulonglong2*)sW0[b][0];
            const ulonglong2* w1r = (const ulonglong2*)sW0[b][1];
            const ulonglong2* w2r = (const ulonglong2*)sW0[b][2];
#pragma unroll
            for (int j2 = 0; j2 < 8; j2++) {
                ulonglong2 wv0 = w0r[j2];
                ulonglong2 wv1 = w1r[j2];
                ulonglong2 wv2 = w2r[j2];
                acc[2 * j2]     = fma2(xx0, wv0.x, acc[2 * j2]);
                acc[2 * j2 + 1] = fma2(xx0, wv0.y, acc[2 * j2 + 1]);
                acc[2 * j2]     = fma2(xx1, wv1.x, acc[2 * j2]);
                acc[2 * j2 + 1] = fma2(xx1, wv1.y, acc[2 * j2 + 1]);
                acc[2 * j2]     = fma2(xx2, wv2.x, acc[2 * j2]);
                acc[2 * j2 + 1] = fma2(xx2, wv2.y, acc[2 * j2 + 1]);
            }
        }
        float ha[HID];
#pragma unroll
        for (int j = 0; j < 16; j++) {
            float lo, hi;
            unpack2(acc[j], lo, hi);
            ha[2 * j]     = fast_tanh(lo);
            ha[2 * j + 1] = fast_tanh(hi);
        }

        // ---- layer 1 and layer 2: 32 -> 32, tanh ----
        float hb[HID];
        dense32_tanh(&sW1[b][0][0], sb1[b], ha, hb);
        dense32_tanh(&sW2[b][0][0], sb2[b], hb, ha);

        // ---- layer 3: 32 -> 1 ----
        float o = sb3[b];
        const float* w3 = sW3[b];
#pragma unroll
        for (int d = 0; d < HID; d++) o = fmaf(ha[d], w3[d], o);

        out[idx * NB + b] = o;
    }
}

extern "C" void kernel_launch(void* const* d_in, const int* in_sizes, int n_in,
                              void* d_out, int out_size) {
    const float* x   = (const float*)d_in[0];
    const float* W0  = (const float*)d_in[1];
    const float* b0  = (const float*)d_in[2];
    const float* W1  = (const float*)d_in[3];
    const float* b1  = (const float*)d_in[4];
    const float* W2  = (const float*)d_in[5];
    const float* b2  = (const float*)d_in[6];
    const float* W3  = (const float*)d_in[7];
    const float* b3  = (const float*)d_in[8];
    float* out = (float*)d_out;

    const int n = in_sizes[0] / 3;
    const int blocks = (n + NTHREADS - 1) / NTHREADS;
    pfnn_kernel<<<blocks, NTHREADS>>>(x, W0, b0, W1, b1, W2, b2, W3, b3, out, n);
}